// round 1
// baseline (speedup 1.0000x reference)
#include <cuda_runtime.h>
#include <cuda_bf16.h>
#include <cstdint>

// Problem constants
#define D_MODEL 1024
#define HID     4096
#define N_KEYS  65536
#define TOP_K   6

#define NEG_INF (-3.402823466e38f)

// Scratch (no device allocation allowed)
__device__ float g_q[HID];
__device__ float g_v[D_MODEL];
__device__ float g_scores[N_KEYS];

// ---------------------------------------------------------------------------
// Kernel 1: q = Wq @ query + bq   (warp per output row), also zero g_v
// ---------------------------------------------------------------------------
__global__ void k_q(const float* __restrict__ Wq,
                    const float* __restrict__ bq,
                    const float* __restrict__ query) {
    if (blockIdx.x == 0) {
        for (int i = threadIdx.x; i < D_MODEL; i += blockDim.x) g_v[i] = 0.0f;
    }
    const int warp = (blockIdx.x * blockDim.x + threadIdx.x) >> 5;  // 0..4095
    const int lane = threadIdx.x & 31;

    const float4* w = reinterpret_cast<const float4*>(Wq + (size_t)warp * D_MODEL);
    const float4* qv = reinterpret_cast<const float4*>(query);

    float acc = 0.0f;
#pragma unroll
    for (int i = 0; i < 8; i++) {
        float4 a = w[lane + 32 * i];
        float4 b = qv[lane + 32 * i];
        acc += a.x * b.x + a.y * b.y + a.z * b.z + a.w * b.w;
    }
#pragma unroll
    for (int o = 16; o > 0; o >>= 1) acc += __shfl_xor_sync(0xFFFFFFFFu, acc, o);
    if (lane == 0) g_q[warp] = acc + bq[warp];
}

// ---------------------------------------------------------------------------
// Kernel 2: v[d] = sum_h Wk[h][d] * q[h]
// 128 blocks x 32 h-rows each; 256 threads own 4 consecutive d (float4);
// atomicAdd partials into g_v (128 adds per address max).
// ---------------------------------------------------------------------------
__global__ void k_v(const float* __restrict__ Wk) {
    const int h0 = blockIdx.x * 32;
    const int t = threadIdx.x;  // 0..255 -> float4 index

    __shared__ float sq[32];
    if (t < 32) sq[t] = g_q[h0 + t];
    __syncthreads();

    float4 acc = make_float4(0.f, 0.f, 0.f, 0.f);
#pragma unroll 8
    for (int j = 0; j < 32; j++) {
        float qh = sq[j];
        float4 w = reinterpret_cast<const float4*>(Wk + (size_t)(h0 + j) * D_MODEL)[t];
        acc.x += w.x * qh;
        acc.y += w.y * qh;
        acc.z += w.z * qh;
        acc.w += w.w * qh;
    }
    atomicAdd(&g_v[t * 4 + 0], acc.x);
    atomicAdd(&g_v[t * 4 + 1], acc.y);
    atomicAdd(&g_v[t * 4 + 2], acc.z);
    atomicAdd(&g_v[t * 4 + 3], acc.w);
}

// ---------------------------------------------------------------------------
// Kernel 3: scores[n] = key_mat[n] . v    (warp per row; v staged in smem)
// 8192 blocks x 256 threads (8 warps/block). Dominant: 256 MB stream.
// ---------------------------------------------------------------------------
__global__ void k_scores(const float* __restrict__ key_mat) {
    __shared__ float4 sv[D_MODEL / 4];
    sv[threadIdx.x] = reinterpret_cast<const float4*>(g_v)[threadIdx.x];
    __syncthreads();

    const int warp = threadIdx.x >> 5;
    const int lane = threadIdx.x & 31;
    const int row = blockIdx.x * 8 + warp;

    const float4* kr = reinterpret_cast<const float4*>(key_mat + (size_t)row * D_MODEL);

    float acc = 0.0f;
#pragma unroll
    for (int i = 0; i < 8; i++) {
        float4 a = kr[lane + 32 * i];
        float4 b = sv[lane + 32 * i];
        acc += a.x * b.x + a.y * b.y + a.z * b.z + a.w * b.w;
    }
#pragma unroll
    for (int o = 16; o > 0; o >>= 1) acc += __shfl_xor_sync(0xFFFFFFFFu, acc, o);
    if (lane == 0) g_scores[row] = acc;
}

// ---------------------------------------------------------------------------
// Kernel 4: top-6 of scores, then out = mean(key_mat[idx]) over the 6 rows.
// Single block, 1024 threads. Each thread keeps a local sorted top-6 over its
// 64 scores; 6 block-argmax rounds merge the 1024 candidates.
// ---------------------------------------------------------------------------
__global__ void k_topk_mean(const float* __restrict__ key_mat,
                            float* __restrict__ out) {
    const int t = threadIdx.x;  // 0..1023

    float lv[TOP_K];
    int li[TOP_K];
#pragma unroll
    for (int j = 0; j < TOP_K; j++) { lv[j] = NEG_INF; li[j] = -1; }

    const float4* s4 = reinterpret_cast<const float4*>(g_scores);
#pragma unroll 4
    for (int i = 0; i < 16; i++) {
        int i4 = t + 1024 * i;          // coalesced
        float4 x = s4[i4];
        float vals[4] = {x.x, x.y, x.z, x.w};
#pragma unroll
        for (int c = 0; c < 4; c++) {
            float xv = vals[c];
            if (xv > lv[TOP_K - 1]) {
                int id = i4 * 4 + c;
                int j = TOP_K - 1;
                while (j > 0 && xv > lv[j - 1]) {
                    lv[j] = lv[j - 1];
                    li[j] = li[j - 1];
                    j--;
                }
                lv[j] = xv;
                li[j] = id;
            }
        }
    }

    __shared__ float sval[1024];
    __shared__ int skey[1024];
    __shared__ int swin[TOP_K];

    int p = 0;  // how many of my local top-6 already consumed
    for (int r = 0; r < TOP_K; r++) {
        sval[t] = (p < TOP_K) ? lv[p] : NEG_INF;
        skey[t] = (p < TOP_K) ? li[p] : -1;
        __syncthreads();
#pragma unroll
        for (int s = 512; s > 0; s >>= 1) {
            if (t < s) {
                if (sval[t + s] > sval[t]) {
                    sval[t] = sval[t + s];
                    skey[t] = skey[t + s];
                }
            }
            __syncthreads();
        }
        float wval = sval[0];
        int wkey = skey[0];
        if (t == 0) swin[r] = wkey;
        __syncthreads();
        if (p < TOP_K && li[p] == wkey && lv[p] == wval) p++;
        __syncthreads();
    }

    // mean of the 6 selected rows
    float s = 0.0f;
#pragma unroll
    for (int j = 0; j < TOP_K; j++) {
        s += key_mat[(size_t)swin[j] * D_MODEL + t];
    }
    out[t] = s * (1.0f / 6.0f);
}

// ---------------------------------------------------------------------------
extern "C" void kernel_launch(void* const* d_in, const int* in_sizes, int n_in,
                              void* d_out, int out_size) {
    const float* query   = (const float*)d_in[0];  // [1024]
    const float* key_mat = (const float*)d_in[1];  // [65536, 1024]
    const float* Wq      = (const float*)d_in[2];  // [4096, 1024]
    const float* bq      = (const float*)d_in[3];  // [4096]
    const float* Wk      = (const float*)d_in[4];  // [4096, 1024]
    // d_in[5] = bk: mathematically irrelevant to top-k indices (constant shift)
    float* out = (float*)d_out;                    // [1024] f32

    k_q<<<512, 256>>>(Wq, bq, query);       // 4096 warps, one per row
    k_v<<<128, 256>>>(Wk);                  // 32 h-rows per block
    k_scores<<<N_KEYS / 8, 256>>>(key_mat); // warp per key row
    k_topk_mean<<<1, 1024>>>(key_mat, out);
}

// round 2
// speedup vs baseline: 1.6430x; 1.6430x over previous
#include <cuda_runtime.h>
#include <cuda_bf16.h>
#include <cstdint>

// Problem constants
#define D_MODEL 1024
#define HID     4096
#define N_KEYS  65536
#define TOP_K   6

#define NEG_INF (-3.402823466e38f)

#define TK_BLOCKS 64                      // stage-1 blocks
#define TK_PER_BLOCK (N_KEYS / TK_BLOCKS) // 1024 scores per block
#define N_CAND (TK_BLOCKS * TOP_K)        // 384 candidates

// Scratch (no device allocation allowed)
__device__ float g_q[HID];
__device__ float g_v[D_MODEL];
__device__ float g_scores[N_KEYS];
__device__ float g_cval[N_CAND];
__device__ int   g_cidx[N_CAND];

// ---------------------------------------------------------------------------
// warp argmax over (val, idx) — returns winner in all lanes
// ---------------------------------------------------------------------------
__device__ __forceinline__ void warp_argmax(float& v, int& i) {
#pragma unroll
    for (int o = 16; o > 0; o >>= 1) {
        float ov = __shfl_xor_sync(0xFFFFFFFFu, v, o);
        int   oi = __shfl_xor_sync(0xFFFFFFFFu, i, o);
        if (ov > v || (ov == v && oi < i)) { v = ov; i = oi; }
    }
}

// ---------------------------------------------------------------------------
// Kernel 1: q = Wq @ query + bq   (warp per output row), also zero g_v
// ---------------------------------------------------------------------------
__global__ void k_q(const float* __restrict__ Wq,
                    const float* __restrict__ bq,
                    const float* __restrict__ query) {
    if (blockIdx.x == 0) {
        for (int i = threadIdx.x; i < D_MODEL; i += blockDim.x) g_v[i] = 0.0f;
    }
    const int warp = (blockIdx.x * blockDim.x + threadIdx.x) >> 5;  // 0..4095
    const int lane = threadIdx.x & 31;

    const float4* w = reinterpret_cast<const float4*>(Wq + (size_t)warp * D_MODEL);
    const float4* qv = reinterpret_cast<const float4*>(query);

    float acc = 0.0f;
#pragma unroll
    for (int i = 0; i < 8; i++) {
        float4 a = w[lane + 32 * i];
        float4 b = qv[lane + 32 * i];
        acc += a.x * b.x + a.y * b.y + a.z * b.z + a.w * b.w;
    }
#pragma unroll
    for (int o = 16; o > 0; o >>= 1) acc += __shfl_xor_sync(0xFFFFFFFFu, acc, o);
    if (lane == 0) g_q[warp] = acc + bq[warp];
}

// ---------------------------------------------------------------------------
// Kernel 2: v[d] = sum_h Wk[h][d] * q[h]
// 128 blocks x 32 h-rows each; 256 threads own 4 consecutive d (float4);
// atomicAdd partials into g_v.
// ---------------------------------------------------------------------------
__global__ void k_v(const float* __restrict__ Wk) {
    const int h0 = blockIdx.x * 32;
    const int t = threadIdx.x;  // 0..255 -> float4 index

    __shared__ float sq[32];
    if (t < 32) sq[t] = g_q[h0 + t];
    __syncthreads();

    float4 acc = make_float4(0.f, 0.f, 0.f, 0.f);
#pragma unroll 8
    for (int j = 0; j < 32; j++) {
        float qh = sq[j];
        float4 w = reinterpret_cast<const float4*>(Wk + (size_t)(h0 + j) * D_MODEL)[t];
        acc.x += w.x * qh;
        acc.y += w.y * qh;
        acc.z += w.z * qh;
        acc.w += w.w * qh;
    }
    atomicAdd(&g_v[t * 4 + 0], acc.x);
    atomicAdd(&g_v[t * 4 + 1], acc.y);
    atomicAdd(&g_v[t * 4 + 2], acc.z);
    atomicAdd(&g_v[t * 4 + 3], acc.w);
}

// ---------------------------------------------------------------------------
// Kernel 3: scores[n] = key_mat[n] . v    (warp per row; v staged in smem)
// ---------------------------------------------------------------------------
__global__ void k_scores(const float* __restrict__ key_mat) {
    __shared__ float4 sv[D_MODEL / 4];
    sv[threadIdx.x] = reinterpret_cast<const float4*>(g_v)[threadIdx.x];
    __syncthreads();

    const int warp = threadIdx.x >> 5;
    const int lane = threadIdx.x & 31;
    const int row = blockIdx.x * 8 + warp;

    const float4* kr = reinterpret_cast<const float4*>(key_mat + (size_t)row * D_MODEL);

    float acc = 0.0f;
#pragma unroll
    for (int i = 0; i < 8; i++) {
        float4 a = kr[lane + 32 * i];
        float4 b = sv[lane + 32 * i];
        acc += a.x * b.x + a.y * b.y + a.z * b.z + a.w * b.w;
    }
#pragma unroll
    for (int o = 16; o > 0; o >>= 1) acc += __shfl_xor_sync(0xFFFFFFFFu, acc, o);
    if (lane == 0) g_scores[row] = acc;
}

// ---------------------------------------------------------------------------
// Kernel 4 (stage 1): per-block top-6 over 1024 scores -> 6 candidates/block.
// Each thread holds 4 values STATICALLY sorted in registers (no local mem).
// 6 rounds: warp shuffle argmax + 8-warp merge; owner pops its head.
// ---------------------------------------------------------------------------
__global__ void k_topk_stage1() {
    const int t = threadIdx.x;            // 0..255
    const int lane = t & 31;
    const int warp = t >> 5;              // 0..7
    const int base = blockIdx.x * TK_PER_BLOCK;

    float4 x = reinterpret_cast<const float4*>(g_scores + base)[t];
    float v0 = x.x, v1 = x.y, v2 = x.z, v3 = x.w;
    int i0 = base + t * 4 + 0, i1 = base + t * 4 + 1,
        i2 = base + t * 4 + 2, i3 = base + t * 4 + 3;

    // sort 4 descending (static compare-swap network)
#define CSWP(a, b, ia, ib) { if (b > a) { float tv = a; a = b; b = tv; int ti = ia; ia = ib; ib = ti; } }
    CSWP(v0, v2, i0, i2); CSWP(v1, v3, i1, i3);
    CSWP(v0, v1, i0, i1); CSWP(v2, v3, i2, i3);
    CSWP(v1, v2, i1, i2);
#undef CSWP

    __shared__ float swv[8];
    __shared__ int   swi[8];
    __shared__ float s_wv;
    __shared__ int   s_wi;

#pragma unroll
    for (int r = 0; r < TOP_K; r++) {
        float bv = v0; int bi = i0;
        warp_argmax(bv, bi);
        if (lane == 0) { swv[warp] = bv; swi[warp] = bi; }
        __syncthreads();
        if (warp == 0) {
            float mv = (lane < 8) ? swv[lane] : NEG_INF;
            int   mi = (lane < 8) ? swi[lane] : -1;
            warp_argmax(mv, mi);
            if (lane == 0) {
                s_wv = mv; s_wi = mi;
                g_cval[blockIdx.x * TOP_K + r] = mv;
                g_cidx[blockIdx.x * TOP_K + r] = mi;
            }
        }
        __syncthreads();
        if (i0 == s_wi) {  // pop head (indices unique -> exactly one owner)
            v0 = v1; i0 = i1;
            v1 = v2; i1 = i2;
            v2 = v3; i2 = i3;
            v3 = NEG_INF; i3 = -1;
        }
        __syncthreads();
    }
}

// ---------------------------------------------------------------------------
// Kernel 5 (stage 2): merge 384 candidates -> global top-6, then
// out = mean(key_mat[idx]).  1 block, 1024 threads, 1 candidate/thread.
// ---------------------------------------------------------------------------
__global__ void k_topk_mean2(const float* __restrict__ key_mat,
                             float* __restrict__ out) {
    const int t = threadIdx.x;   // 0..1023
    const int lane = t & 31;
    const int warp = t >> 5;     // 0..31

    float v = (t < N_CAND) ? g_cval[t] : NEG_INF;
    int   i = (t < N_CAND) ? g_cidx[t] : -1;

    __shared__ float swv[32];
    __shared__ int   swi[32];
    __shared__ int   s_win[TOP_K];
    __shared__ int   s_wi;

#pragma unroll
    for (int r = 0; r < TOP_K; r++) {
        float bv = v; int bi = i;
        warp_argmax(bv, bi);
        if (lane == 0) { swv[warp] = bv; swi[warp] = bi; }
        __syncthreads();
        if (warp == 0) {
            float mv = swv[lane];
            int   mi = swi[lane];
            warp_argmax(mv, mi);
            if (lane == 0) { s_wi = mi; s_win[r] = mi; }
        }
        __syncthreads();
        if (i == s_wi) v = NEG_INF;  // remove winner
        __syncthreads();
    }

    // mean of the 6 selected rows (t indexes the 1024 output elements)
    float s = 0.0f;
#pragma unroll
    for (int j = 0; j < TOP_K; j++) {
        s += key_mat[(size_t)s_win[j] * D_MODEL + t];
    }
    out[t] = s * (1.0f / 6.0f);
}

// ---------------------------------------------------------------------------
extern "C" void kernel_launch(void* const* d_in, const int* in_sizes, int n_in,
                              void* d_out, int out_size) {
    const float* query   = (const float*)d_in[0];  // [1024]
    const float* key_mat = (const float*)d_in[1];  // [65536, 1024]
    const float* Wq      = (const float*)d_in[2];  // [4096, 1024]
    const float* bq      = (const float*)d_in[3];  // [4096]
    const float* Wk      = (const float*)d_in[4];  // [4096, 1024]
    // d_in[5] = bk: constant shift of all scores -> top-k indices unchanged
    float* out = (float*)d_out;                    // [1024] f32

    k_q<<<512, 256>>>(Wq, bq, query);        // 4096 warps, one per row
    k_v<<<128, 256>>>(Wk);                   // 32 h-rows per block
    k_scores<<<N_KEYS / 8, 256>>>(key_mat);  // warp per key row
    k_topk_stage1<<<TK_BLOCKS, 256>>>();     // 384 candidates
    k_topk_mean2<<<1, 1024>>>(key_mat, out); // merge + gather-mean
}